// round 5
// baseline (speedup 1.0000x reference)
#include <cuda_runtime.h>
#include <math.h>

#define BB 16
#define PP 500
#define NN 501
#define EE 128
#define HH 8
#define HD 16
#define LL 3
#define LEAKY 0.2f
#define LN_EPS 1e-5f
#define ADJ_CNT (BB * NN * NN)
#define IT 16
#define JT 16
#define MW 16   // mask words per row (501 bits -> 16 u32)

// Scratch (device globals; no runtime allocation)
__device__ float g_x[2][(size_t)BB * NN * EE];
__device__ float g_xW[(size_t)BB * NN * EE];
__device__ float g_ei[BB * NN * HH];
__device__ float g_ej[BB * NN * HH];
__device__ unsigned char g_adj[ADJ_CNT];
__device__ int g_mask_kind;

__device__ __forceinline__ void ffma2(unsigned long long& acc,
                                      unsigned long long x,
                                      unsigned long long p) {
    asm("fma.rn.f32x2 %0, %1, %2, %0;" : "+l"(acc) : "l"(x), "l"(p));
}
__device__ __forceinline__ float2 u2f2(unsigned long long u) {
    float2 r;
    r.x = __uint_as_float((unsigned)u);
    r.y = __uint_as_float((unsigned)(u >> 32));
    return r;
}

// ---------------------------------------------------------------------------
__global__ void probe_mask_kernel(const unsigned int* __restrict__ w) {
    __shared__ int s_u8, s_f32;
    if (threadIdx.x == 0) { s_u8 = 0; s_f32 = 0; }
    __syncthreads();
    for (int idx = threadIdx.x; idx < 4096; idx += blockDim.x) {
        unsigned int v = w[idx];
        if (v == 0x3f800000u) atomicOr(&s_f32, 1);
        else if (v > 1u)      atomicOr(&s_u8, 1);
    }
    __syncthreads();
    if (threadIdx.x == 0) g_mask_kind = s_f32 ? 2 : (s_u8 ? 1 : 0);
}

__global__ void convert_mask_kernel(const void* __restrict__ adj_raw) {
    int i = blockIdx.x * blockDim.x + threadIdx.x;
    if (i >= ADJ_CNT) return;
    int kind = g_mask_kind;
    unsigned char v;
    if (kind == 1)      v = ((const unsigned char*)adj_raw)[i] ? 1 : 0;
    else if (kind == 2) v = (((const float*)adj_raw)[i] != 0.0f) ? 1 : 0;
    else                v = (((const int*)adj_raw)[i] != 0) ? 1 : 0;
    g_adj[i] = v;
}

// ---------------------------------------------------------------------------
__global__ void embed_kernel(const float* __restrict__ depot_xy,
                             const float* __restrict__ node5,
                             const float* __restrict__ depW,
                             const float* __restrict__ depb,
                             const float* __restrict__ nodeW,
                             const float* __restrict__ nodeb) {
    int bn = blockIdx.x;
    int b = bn / NN, n = bn % NN;
    int e = threadIdx.x;
    float v;
    if (n == 0) {
        float x0 = depot_xy[b * 2 + 0];
        float x1 = depot_xy[b * 2 + 1];
        v = fmaf(x0, depW[0 * EE + e], fmaf(x1, depW[1 * EE + e], depb[e]));
    } else {
        int p = n - 1;
        const float* f = node5 + ((size_t)b * PP + p) * 5;
        v = nodeb[e];
        #pragma unroll
        for (int k = 0; k < 5; k++) v = fmaf(f[k], nodeW[k * EE + e], v);
    }
    g_x[0][(size_t)bn * EE + e] = v;
}

// ---------------------------------------------------------------------------
// xW = x @ W[l] + fused ei/ej. grid = 501, block = 256, 16 rows/block.
// ---------------------------------------------------------------------------
__global__ void __launch_bounds__(256) xw_kernel(int src,
                                                const float* __restrict__ Wl,
                                                const float* __restrict__ attn_l) {
    int t = threadIdx.x;
    int e = t & 127, half = t >> 7;
    int row0 = blockIdx.x * 16;
    __shared__ float xs[16][EE];
    const float* x = &g_x[src][0];
    {
        const float4* s4 = (const float4*)(x + (size_t)row0 * EE);
        float4* d4 = (float4*)&xs[0][0];
        for (int idx = t; idx < 16 * EE / 4; idx += 256) d4[idx] = s4[idx];
    }
    __syncthreads();

    float acc[8];
    #pragma unroll
    for (int r = 0; r < 8; r++) acc[r] = 0.f;

    for (int k = 0; k < EE; k += 4) {
        float w0 = Wl[(k + 0) * EE + e];
        float w1 = Wl[(k + 1) * EE + e];
        float w2 = Wl[(k + 2) * EE + e];
        float w3 = Wl[(k + 3) * EE + e];
        #pragma unroll
        for (int r = 0; r < 8; r++) {
            float4 xv = *(const float4*)&xs[half * 8 + r][k];
            acc[r] = fmaf(xv.x, w0, acc[r]);
            acc[r] = fmaf(xv.y, w1, acc[r]);
            acc[r] = fmaf(xv.z, w2, acc[r]);
            acc[r] = fmaf(xv.w, w3, acc[r]);
        }
    }

    int h = e >> 4, d = e & 15;
    float a1 = attn_l[h * 2 * HD + d];
    float a2 = attn_l[h * 2 * HD + HD + d];
    #pragma unroll
    for (int r = 0; r < 8; r++) {
        int row = row0 + half * 8 + r;
        g_xW[(size_t)row * EE + e] = acc[r];
        float vi = acc[r] * a1, vj = acc[r] * a2;
        #pragma unroll
        for (int off = 8; off; off >>= 1) {
            vi += __shfl_down_sync(0xffffffffu, vi, off, 16);
            vj += __shfl_down_sync(0xffffffffu, vj, off, 16);
        }
        if (d == 0) { g_ei[row * HH + h] = vi; g_ej[row * HH + h] = vj; }
    }
}

// ---------------------------------------------------------------------------
// Attention + residual + LayerNorm + ELU, f32x2 inner loop.
// grid = (32, B), block = 256. Warp w owns rows i0+2w, i0+2w+1; lane = 4 cols.
// ---------------------------------------------------------------------------
__global__ void __launch_bounds__(256) attn_kernel(const float* __restrict__ gamma,
                                                   const float* __restrict__ beta,
                                                   int dst, float* __restrict__ dout) {
    int b = blockIdx.y;
    int i0 = blockIdx.x * IT;
    int t = threadIdx.x;

    __shared__ float ej_s[NN * HH];                 // 16032 B
    __shared__ float ei_s[IT * HH];
    __shared__ float m_s[IT * HH];
    __shared__ float mred[2][IT * HH];
    __shared__ float s_s[IT * HH];
    __shared__ unsigned int mask_s[IT][MW];         // 1024 B
    __shared__ float xs[JT][EE];                    // 8192 B
    __shared__ unsigned long long p2[JT][IT * HH];  // 16384 B

    const float* xWb = g_xW + (size_t)b * NN * EE;
    const unsigned char* adjb = g_adj + (size_t)b * NN * NN;

    for (int idx = t; idx < NN * HH; idx += 256) ej_s[idx] = g_ej[b * NN * HH + idx];
    for (int idx = t; idx < IT * HH; idx += 256) {
        int i = i0 + (idx >> 3);
        ei_s[idx] = (i < NN) ? g_ei[(b * NN + i) * HH + (idx & 7)] : 0.f;
    }
    // bitmask staging: one u32 word per thread
    {
        int idx = t;  // 256 = IT*MW exactly
        int ii = idx >> 4, w = idx & 15;
        int i = i0 + ii;
        unsigned int bits = 0;
        if (i < NN) {
            const unsigned char* row = adjb + (size_t)i * NN;
            int jb = w * 32;
            #pragma unroll 8
            for (int k = 0; k < 32; k++) {
                int j = jb + k;
                if (j < NN && row[j]) bits |= (1u << k);
            }
        }
        mask_s[ii][w] = bits;
    }
    __syncthreads();

    // Pass A: m[i,h] = leaky(ei + max_{adj} ej)   (leaky is monotone)
    {
        int p = t & 127, half = t >> 7;
        int ii = p >> 3, hh = p & 7;
        int jb = half ? 251 : 0, je = half ? NN : 251;
        float mx = -INFINITY;
        for (int j = jb; j < je; j++)
            if ((mask_s[ii][j >> 5] >> (j & 31)) & 1u)
                mx = fmaxf(mx, ej_s[j * HH + hh]);
        mred[half][p] = mx;
    }
    __syncthreads();
    if (t < IT * HH) {
        float w = ei_s[t] + fmaxf(mred[0][t], mred[1][t]);
        m_s[t] = (w >= 0.f) ? w : LEAKY * w;
    }
    __syncthreads();

    // Pass B
    int c4 = t & 31;          // cols 4*c4 .. 4*c4+3
    int warp = t >> 5;        // rows warp*2, warp*2+1
    int h = c4 >> 2;
    bool sowner = ((c4 & 3) == 0);
    unsigned long long acc64[2][2] = {{0ull, 0ull}, {0ull, 0ull}};
    float sacc[2] = {0.f, 0.f};

    for (int j0 = 0; j0 < NN; j0 += JT) {
        // stage xW j-tile
        {
            float4* d4 = (float4*)&xs[0][0];
            for (int idx = t; idx < JT * EE / 4; idx += 256) {
                int jj = idx >> 5;
                int j = j0 + jj;
                d4[idx] = (j < NN) ? ((const float4*)(xWb + (size_t)j * EE))[idx & 31]
                                   : make_float4(0.f, 0.f, 0.f, 0.f);
            }
        }
        // p (packed twice) for this tile
        for (int idx = t; idx < JT * IT * HH; idx += 256) {
            int jj = idx >> 7, ph = idx & 127;
            int ii = ph >> 3, hh = ph & 7;
            int j = j0 + jj;
            float val = 0.f;
            if (j < NN && ((mask_s[ii][j >> 5] >> (j & 31)) & 1u)) {
                float w = ei_s[ph] + ej_s[j * HH + hh];
                w = (w >= 0.f) ? w : LEAKY * w;
                val = __expf(w - m_s[ph]);
            }
            unsigned int u = __float_as_uint(val);
            p2[jj][ph] = ((unsigned long long)u << 32) | u;
        }
        __syncthreads();

        #pragma unroll 4
        for (int jj = 0; jj < JT; jj++) {
            ulonglong2 xv = *(const ulonglong2*)&xs[jj][4 * c4];
            #pragma unroll
            for (int r = 0; r < 2; r++) {
                unsigned long long pv = p2[jj][(warp * 2 + r) * HH + h];
                ffma2(acc64[r][0], xv.x, pv);
                ffma2(acc64[r][1], xv.y, pv);
                if (sowner) sacc[r] += __uint_as_float((unsigned)pv);
            }
        }
        __syncthreads();
    }

    if (sowner) {
        #pragma unroll
        for (int r = 0; r < 2; r++) s_s[(warp * 2 + r) * HH + h] = sacc[r];
    }
    __syncthreads();

    // Epilogue: normalize, residual, LayerNorm (warp-local bfly), ELU
    float* o = (dst < 0) ? dout : &g_x[dst][0];
    float4 gv = *(const float4*)&gamma[4 * c4];
    float4 bv = *(const float4*)&beta[4 * c4];

    #pragma unroll
    for (int r = 0; r < 2; r++) {
        int ii = warp * 2 + r;
        int i = i0 + ii;
        if (i >= NN) continue;
        float inv = 1.f / s_s[ii * HH + h];
        float4 xwv = *(const float4*)(xWb + (size_t)i * EE + 4 * c4);
        float2 lo = u2f2(acc64[r][0]);
        float2 hi = u2f2(acc64[r][1]);
        float v0 = lo.x * inv + xwv.x;
        float v1 = lo.y * inv + xwv.y;
        float v2 = hi.x * inv + xwv.z;
        float v3 = hi.y * inv + xwv.w;

        float s1 = v0 + v1 + v2 + v3;
        float s2 = v0 * v0 + v1 * v1 + v2 * v2 + v3 * v3;
        #pragma unroll
        for (int off = 16; off; off >>= 1) {
            s1 += __shfl_xor_sync(0xffffffffu, s1, off);
            s2 += __shfl_xor_sync(0xffffffffu, s2, off);
        }
        float mu = s1 * (1.f / EE);
        float var = s2 * (1.f / EE) - mu * mu;
        float rstd = rsqrtf(var + LN_EPS);

        float y0 = (v0 - mu) * rstd * gv.x + bv.x;
        float y1 = (v1 - mu) * rstd * gv.y + bv.y;
        float y2 = (v2 - mu) * rstd * gv.z + bv.z;
        float y3 = (v3 - mu) * rstd * gv.w + bv.w;
        y0 = y0 > 0.f ? y0 : expm1f(y0);
        y1 = y1 > 0.f ? y1 : expm1f(y1);
        y2 = y2 > 0.f ? y2 : expm1f(y2);
        y3 = y3 > 0.f ? y3 : expm1f(y3);
        *(float4*)(o + ((size_t)(b * NN + i)) * EE + 4 * c4) =
            make_float4(y0, y1, y2, y3);
    }
}

// ---------------------------------------------------------------------------
extern "C" void kernel_launch(void* const* d_in, const int* in_sizes, int n_in,
                              void* d_out, int out_size) {
    const float* depot_xy = (const float*)d_in[0];
    const float* node5    = (const float*)d_in[1];
    const void*  adj_raw  = (const void*)d_in[2];
    const float* depW  = (const float*)d_in[3];
    const float* depb  = (const float*)d_in[4];
    const float* nodeW = (const float*)d_in[5];
    const float* nodeb = (const float*)d_in[6];
    const float* W     = (const float*)d_in[7];
    const float* attn  = (const float*)d_in[8];
    const float* ln_g  = (const float*)d_in[9];
    const float* ln_b  = (const float*)d_in[10];
    float* out = (float*)d_out;

    probe_mask_kernel<<<1, 256>>>((const unsigned int*)adj_raw);
    convert_mask_kernel<<<(ADJ_CNT + 255) / 256, 256>>>(adj_raw);

    embed_kernel<<<BB * NN, EE>>>(depot_xy, node5, depW, depb, nodeW, nodeb);

    dim3 agrid((NN + IT - 1) / IT, BB);
    int cur = 0;
    for (int l = 0; l < LL; l++) {
        xw_kernel<<<BB * NN / 16, 256>>>(cur,
                                         W + (size_t)l * EE * EE,
                                         attn + (size_t)l * HH * 2 * HD);
        int dst = (l == LL - 1) ? -1 : (1 - cur);
        attn_kernel<<<agrid, 256>>>(ln_g + (size_t)l * EE,
                                    ln_b + (size_t)l * EE,
                                    dst, out);
        cur = 1 - cur;
    }
}